// round 3
// baseline (speedup 1.0000x reference)
#include <cuda_runtime.h>

#define NN 100000
#define EE 1600000
#define GG 2000
#define BN_EPS 1e-5f

// ---------------- scratch (static device globals; no runtime alloc) ----------------
__device__ __align__(16) float d_cat[NN * 256];   // cols [0:128)=s=A@h, cols [128:256)=h
__device__ __align__(16) float d_act[NN * 256];   // GEMM output (pre/post BN)
__device__ int   d_flag;            // 1 = inputs are int64, 0 = int32
__device__ int   d_row[EE];
__device__ int   d_colv[EE];
__device__ int   d_bat[NN];
__device__ int   d_deg[NN];
__device__ float d_dinv[NN];
__device__ int   d_off[NN + 1];
__device__ int   d_cur[NN];
__device__ int   d_src[EE];
__device__ float d_nrm[EE];
__device__ int   d_goff[GG + 1];
__device__ __align__(16) float d_Wcat[5 * 256 * 128 + 256 * 256];  // [Wi;Wr] per layer, [256,F] row-major
__device__ float d_stats[512];                    // [0:256)=sum, [256:512)=sumsq

// ---------------- dtype detection: int64 buffers have zero hi-words ----------------
__global__ void k_detect(const unsigned int* __restrict__ buf) {
    // Sample odd 32-bit words among the first 2*EE words (safe for both dtypes).
    // int64 data (values in [0,2^31)): odd words are hi-words == 0.
    // int32 data: odd words are random node ids, ~surely nonzero somewhere.
    __shared__ int any;
    if (threadIdx.x == 0) any = 0;
    __syncthreads();
    const int S = 2 * EE / 2048;   // stride between sampled elements
    for (int k = threadIdx.x; k < 1024; k += blockDim.x) {
        unsigned int w = buf[2 * (k * S) + 1];
        if (w != 0u) atomicOr(&any, 1);
    }
    __syncthreads();
    if (threadIdx.x == 0) d_flag = (any == 0) ? 1 : 0;
}

__global__ void k_extract(const void* __restrict__ eiv) {
    int e = blockIdx.x * blockDim.x + threadIdx.x;
    if (e >= EE) return;
    int r, c;
    if (d_flag) {
        const long long* p = (const long long*)eiv;
        r = (int)p[e]; c = (int)p[EE + e];
    } else {
        const int* p = (const int*)eiv;
        r = p[e]; c = p[EE + e];
    }
    d_row[e] = r; d_colv[e] = c;
}

__global__ void k_batcvt(const void* __restrict__ bv) {
    int n = blockIdx.x * blockDim.x + threadIdx.x;
    if (n >= NN) return;
    d_bat[n] = d_flag ? (int)((const long long*)bv)[n] : ((const int*)bv)[n];
}

// ---------------- graph preprocessing ----------------
__global__ void k_zero_deg() {
    int i = blockIdx.x * blockDim.x + threadIdx.x;
    if (i < NN) d_deg[i] = 0;
}

__global__ void k_copy_x(const float* __restrict__ x) {
    int i = blockIdx.x * blockDim.x + threadIdx.x;
    if (i < NN * 32) {
        int n = i >> 5, c = i & 31;
        ((float4*)d_cat)[n * 64 + 32 + c] = ((const float4*)x)[i];
    }
}

__global__ void k_count() {
    int e = blockIdx.x * blockDim.x + threadIdx.x;
    if (e < EE) atomicAdd(&d_deg[d_colv[e]], 1);
}

__global__ void k_scan() {   // 1 block, 1024 threads: exclusive scan of deg -> off, cur, dinv
    __shared__ int ssum[1024];
    int t = threadIdx.x;
    const int C = (NN + 1023) / 1024;
    int b0 = t * C, b1 = min(b0 + C, NN);
    int s = 0;
    for (int i = b0; i < b1; i++) s += d_deg[i];
    ssum[t] = s;
    __syncthreads();
    int own = s;
    for (int off = 1; off < 1024; off <<= 1) {
        int v = (t >= off) ? ssum[t - off] : 0;
        __syncthreads();
        ssum[t] += v;
        __syncthreads();
    }
    int run = ssum[t] - own;  // exclusive prefix
    for (int i = b0; i < b1; i++) {
        int d = d_deg[i];
        d_off[i] = run;
        d_cur[i] = run;
        d_dinv[i] = (d > 0) ? rsqrtf((float)d) : 0.0f;
        run += d;
    }
    if (t == 0) d_off[NN] = EE;
}

__global__ void k_fill() {
    int e = blockIdx.x * blockDim.x + threadIdx.x;
    if (e < EE) {
        int r = d_row[e];
        int c = d_colv[e];
        int p = atomicAdd(&d_cur[c], 1);
        d_src[p] = r;
        d_nrm[p] = d_dinv[r] * d_dinv[c];
    }
}

__global__ void k_wcat(const float* __restrict__ Wi, const float* __restrict__ Wr,
                       const float* __restrict__ Wi6, const float* __restrict__ Wr6) {
    int i = blockIdx.x * blockDim.x + threadIdx.x;
    const int L5 = 5 * 256 * 128;
    if (i < L5) {
        int l = i >> 15;
        int rem = i & 32767;
        int k = rem >> 7, f = rem & 127;
        d_Wcat[i] = (k < 128) ? Wi[(l << 14) + (k << 7) + f]
                              : Wr[(l << 14) + ((k - 128) << 7) + f];
    } else if (i < L5 + 65536) {
        int j = i - L5;
        int k = j >> 8, f = j & 255;
        d_Wcat[i] = (k < 128) ? Wi6[(k << 8) + f] : Wr6[((k - 128) << 8) + f];
    }
}

__global__ void k_goff() {   // batch is sorted
    int n = blockIdx.x * blockDim.x + threadIdx.x;
    if (n >= NN) return;
    int bn = d_bat[n];
    int bp = (n == 0) ? -1 : d_bat[n - 1];
    for (int id = bp + 1; id <= bn; id++) d_goff[id] = n;
    if (n == NN - 1)
        for (int id = bn + 1; id <= GG; id++) d_goff[id] = NN;
}

// ---------------- SpMM: s[i,:] = sum_{e: col=i} norm_e * h[row_e,:]  (warp per node) ----------------
__global__ void k_spmm() {
    int w = (blockIdx.x * blockDim.x + threadIdx.x) >> 5;
    int lane = threadIdx.x & 31;
    if (w >= NN) return;
    int s0 = d_off[w], s1 = d_off[w + 1];
    float4 acc = make_float4(0.f, 0.f, 0.f, 0.f);
    const float4* hb = (const float4*)d_cat;   // row = 64 float4, h half at +32
    int k = s0;
    for (; k + 1 < s1; k += 2) {
        int src0 = __ldg(&d_src[k]);
        int src1 = __ldg(&d_src[k + 1]);
        float w0 = __ldg(&d_nrm[k]);
        float w1 = __ldg(&d_nrm[k + 1]);
        float4 v0 = __ldg(&hb[src0 * 64 + 32 + lane]);
        float4 v1 = __ldg(&hb[src1 * 64 + 32 + lane]);
        acc.x = fmaf(w0, v0.x, acc.x); acc.y = fmaf(w0, v0.y, acc.y);
        acc.z = fmaf(w0, v0.z, acc.z); acc.w = fmaf(w0, v0.w, acc.w);
        acc.x = fmaf(w1, v1.x, acc.x); acc.y = fmaf(w1, v1.y, acc.y);
        acc.z = fmaf(w1, v1.z, acc.z); acc.w = fmaf(w1, v1.w, acc.w);
    }
    if (k < s1) {
        int src = __ldg(&d_src[k]);
        float wt = __ldg(&d_nrm[k]);
        float4 v = __ldg(&hb[src * 64 + 32 + lane]);
        acc.x = fmaf(wt, v.x, acc.x); acc.y = fmaf(wt, v.y, acc.y);
        acc.z = fmaf(wt, v.z, acc.z); acc.w = fmaf(wt, v.w, acc.w);
    }
    ((float4*)d_cat)[w * 64 + lane] = acc;
}

// ---------------- SGEMM: act = ReLU(cat[N,256] @ Wcat[256,Nn] + bias), ldc=Nn ----------------
__global__ void __launch_bounds__(256) k_sgemm(int wofs, const float* __restrict__ bias, int Nn) {
    __shared__ float As[2][8][128];
    __shared__ float Bs[2][8][128];
    const float* A = d_cat;
    const float* B = d_Wcat + wofs;
    int tid = threadIdx.x;
    int bm = blockIdx.x * 128, bn = blockIdx.y * 128;
    int tx = tid & 15, ty = tid >> 4;

    float acc[8][8];
#pragma unroll
    for (int i = 0; i < 8; i++)
#pragma unroll
        for (int j = 0; j < 8; j++) acc[i][j] = 0.f;

    int arow = bm + (tid >> 1);
    int akq = (tid & 1) * 4;
    int bkr = tid >> 5, bnq = (tid & 31) * 4;

    float4 av, bv;
    av = (arow < NN) ? *(const float4*)(A + arow * 256 + akq) : make_float4(0.f, 0.f, 0.f, 0.f);
    bv = *(const float4*)(B + bkr * Nn + bn + bnq);
    As[0][akq + 0][tid >> 1] = av.x;
    As[0][akq + 1][tid >> 1] = av.y;
    As[0][akq + 2][tid >> 1] = av.z;
    As[0][akq + 3][tid >> 1] = av.w;
    *(float4*)&Bs[0][bkr][bnq] = bv;
    __syncthreads();

    int buf = 0;
    for (int ks = 0; ks < 32; ks++) {
        int k0n = (ks + 1) * 8;
        if (ks < 31) {
            av = (arow < NN) ? *(const float4*)(A + arow * 256 + k0n + akq)
                             : make_float4(0.f, 0.f, 0.f, 0.f);
            bv = *(const float4*)(B + (k0n + bkr) * Nn + bn + bnq);
        }
#pragma unroll
        for (int k = 0; k < 8; k++) {
            float a[8], b[8];
            *(float4*)&a[0] = *(const float4*)&As[buf][k][ty * 4];
            *(float4*)&a[4] = *(const float4*)&As[buf][k][64 + ty * 4];
            *(float4*)&b[0] = *(const float4*)&Bs[buf][k][tx * 4];
            *(float4*)&b[4] = *(const float4*)&Bs[buf][k][64 + tx * 4];
#pragma unroll
            for (int i = 0; i < 8; i++)
#pragma unroll
                for (int j = 0; j < 8; j++) acc[i][j] = fmaf(a[i], b[j], acc[i][j]);
        }
        if (ks < 31) {
            int nb = buf ^ 1;
            As[nb][akq + 0][tid >> 1] = av.x;
            As[nb][akq + 1][tid >> 1] = av.y;
            As[nb][akq + 2][tid >> 1] = av.z;
            As[nb][akq + 3][tid >> 1] = av.w;
            *(float4*)&Bs[nb][bkr][bnq] = bv;
            __syncthreads();
            buf = nb;
        }
    }

#pragma unroll
    for (int i = 0; i < 8; i++) {
        int m = bm + ((i < 4) ? (ty * 4 + i) : (64 + ty * 4 + i - 4));
        if (m < NN) {
#pragma unroll
            for (int j = 0; j < 8; j++) {
                int n = bn + ((j < 4) ? (tx * 4 + j) : (64 + tx * 4 + j - 4));
                float v = acc[i][j] + bias[n];
                d_act[m * Nn + n] = (v > 0.f) ? v : 0.f;
            }
        }
    }
}

// ---------------- BatchNorm ----------------
__global__ void k_zstats() {
    int i = threadIdx.x;
    if (i < 512) d_stats[i] = 0.f;
}

__global__ void k_bnstats(int F) {
    int f = threadIdx.x;
    float s = 0.f, s2 = 0.f;
    for (int n = blockIdx.x; n < NN; n += gridDim.x) {
        float v = d_act[n * F + f];
        s += v;
        s2 += v * v;
    }
    atomicAdd(&d_stats[f], s);
    atomicAdd(&d_stats[256 + f], s2);
}

__global__ void k_bnapply(const float* __restrict__ g, const float* __restrict__ be,
                          int F, int toCat) {
    int f = threadIdx.x;
    float mu = d_stats[f] * (1.f / NN);
    float var = d_stats[256 + f] * (1.f / NN) - mu * mu;
    float sc = g[f] * rsqrtf(var + BN_EPS);
    float sh = be[f] - mu * sc;
    for (int n = blockIdx.x; n < NN; n += gridDim.x) {
        float v = fmaf(d_act[n * F + f], sc, sh);
        if (toCat) d_cat[n * 256 + 128 + f] = v;
        else       d_act[n * F + f] = v;
    }
}

// ---------------- global add pool (batch sorted => contiguous ranges) ----------------
__global__ void k_pool(float* __restrict__ out) {
    int g = blockIdx.x, f = threadIdx.x;
    int n0 = d_goff[g], n1 = d_goff[g + 1];
    float s = 0.f;
    for (int n = n0; n < n1; n++) s += d_act[n * 256 + f];
    out[g * 256 + f] = s;
}

// ---------------- launch ----------------
extern "C" void kernel_launch(void* const* d_in, const int* in_sizes, int n_in,
                              void* d_out, int out_size) {
    const float* x   = (const float*)d_in[0];
    const void*  ei  = d_in[1];
    const void*  bat = d_in[2];
    const float* Wi  = (const float*)d_in[3];
    const float* Wr  = (const float*)d_in[4];
    const float* b   = (const float*)d_in[5];
    const float* g   = (const float*)d_in[6];
    const float* be  = (const float*)d_in[7];
    const float* Wi6 = (const float*)d_in[8];
    const float* Wr6 = (const float*)d_in[9];
    const float* b6  = (const float*)d_in[10];
    const float* g6  = (const float*)d_in[11];
    const float* be6 = (const float*)d_in[12];
    float* out = (float*)d_out;

    k_detect<<<1, 256>>>((const unsigned int*)ei);
    k_extract<<<(EE + 255) / 256, 256>>>(ei);
    k_batcvt<<<(NN + 255) / 256, 256>>>(bat);

    k_zero_deg<<<(NN + 255) / 256, 256>>>();
    k_copy_x<<<(NN * 32 + 255) / 256, 256>>>(x);
    k_count<<<(EE + 255) / 256, 256>>>();
    k_scan<<<1, 1024>>>();
    k_fill<<<(EE + 255) / 256, 256>>>();
    k_wcat<<<(5 * 32768 + 65536 + 255) / 256, 256>>>(Wi, Wr, Wi6, Wr6);
    k_goff<<<(NN + 255) / 256, 256>>>();

    const int mblocks = (NN + 127) / 128;
    for (int l = 0; l < 5; l++) {
        k_spmm<<<(NN + 7) / 8, 256>>>();
        k_sgemm<<<dim3(mblocks, 1), 256>>>(l * 32768, b + l * 128, 128);
        k_zstats<<<1, 512>>>();
        k_bnstats<<<512, 128>>>(128);
        k_bnapply<<<2048, 128>>>(g + l * 128, be + l * 128, 128, 1);
    }
    // layer 6 (F_OUT = 256)
    k_spmm<<<(NN + 7) / 8, 256>>>();
    k_sgemm<<<dim3(mblocks, 2), 256>>>(5 * 32768, b6, 256);
    k_zstats<<<1, 512>>>();
    k_bnstats<<<512, 256>>>(256);
    k_bnapply<<<2048, 256>>>(g6, be6, 256, 0);

    k_pool<<<GG, 256>>>(out);
}